// round 14
// baseline (speedup 1.0000x reference)
#include <cuda_runtime.h>
#include <math.h>

#define NORI 6

typedef unsigned long long ull;

struct __align__(16) Consts {
  float cst[768];        // [jp][12] = {g0 x2, G0 x2, G1 x2, G2 x2, G3 x2, v2 x2}
  float2 kri[25];        // interleaved (kr, ki)
  float alpha[4], gam[4], p[4];
  float P0;
};
__device__ Consts c_;

__device__ __forceinline__ ull pk(float a, float b){ ull r; asm("mov.b64 %0,{%1,%2};":"=l"(r):"f"(a),"f"(b)); return r; }
__device__ __forceinline__ void upk(ull v, float&a, float&b){ asm("mov.b64 {%0,%1},%2;":"=f"(a),"=f"(b):"l"(v)); }
__device__ __forceinline__ ull fma2(ull a, ull b, ull c){ ull d; asm("fma.rn.f32x2 %0,%1,%2,%3;":"=l"(d):"l"(a),"l"(b),"l"(c)); return d; }

__device__ __forceinline__ float softplusf(float x){
  return (x > 20.f) ? x : log1pf(__expf(x));
}

// ---------------------------------------------------------------------------
// Kernel 1: fold all weights into constants (1 block, 256 thr, smem-staged)
// ---------------------------------------------------------------------------
__global__ void __launch_bounds__(256) precompute_kernel(
  const float* __restrict__ sigma, const float* __restrict__ lambd,
  const float* __restrict__ psi,   const float* __restrict__ gamma_,
  const float* __restrict__ theta, const float* __restrict__ dir_w,
  const float* __restrict__ qw,    const float* __restrict__ qb,
  const float* __restrict__ kvw,   const float* __restrict__ kvb,
  const float* __restrict__ in_w,  const float* __restrict__ in_b,
  const float* __restrict__ ow,    const float* __restrict__ ob,
  const float* __restrict__ m1w,   const float* __restrict__ m1b,
  const float* __restrict__ m2w,   const float* __restrict__ m2b,
  const float* __restrict__ pw,    const float* __restrict__ pb)
{
  __shared__ float pm1w[128*33];       // padded rows: [j][33]
  __shared__ float pm2w[4096];         // linear [e1*128+j]
  __shared__ float pows[32*33];        // padded rows: [e0][33]
  __shared__ float s_pw[32];
  __shared__ float s_w[NORI];
  __shared__ float s_gr[NORI][25], s_gi[NORI][25];
  __shared__ float s_aq[32], s_ak[32], s_av[32], s_cq[32], s_cv[32];
  __shared__ float s_M[4][32], s_b0[32];
  __shared__ float sm_G[4][128], sm_g0[128], sm_v2[128];
  int t = threadIdx.x;

  #pragma unroll
  for (int i=0;i<16;i++){
    int idx = t + (i<<8);
    pm1w[(idx>>5)*33 + (idx&31)] = m1w[idx];
  }
  #pragma unroll
  for (int i=0;i<4;i++){
    ((float4*)pm2w)[t + (i<<8)] = ((const float4*)m2w)[t + (i<<8)];
  }
  #pragma unroll
  for (int i=0;i<4;i++){
    int idx = t + (i<<8);
    pows[(idx>>5)*33 + (idx&31)] = ow[idx];
  }
  if (t<32) s_pw[t] = pw[t];

  if (t==0){
    float mx = dir_w[0];
    for (int o=1;o<NORI;o++) mx = fmaxf(mx, dir_w[o]);
    float e[NORI]; float sum=0.f;
    for (int o=0;o<NORI;o++){ e[o]=__expf(dir_w[o]-mx); sum+=e[o]; }
    float inv = 1.f/sum;
    for (int o=0;o<NORI;o++) s_w[o]=e[o]*inv;
  }
  if (t<150){
    int o = t/25, tap = t-25*o;
    int i = tap/5, j = tap-5*i;
    float yy = -1.f + 0.5f*(float)i;
    float xx = -1.f + 0.5f*(float)j;
    float s  = softplusf(sigma[o])+0.1f;
    float l  = softplusf(lambd[o])+0.1f;
    float g  = softplusf(gamma_[o])+0.1f;
    float th = tanhf(theta[o])*(float)M_PI;
    float ps = tanhf(psi[o])*(float)M_PI;
    float ct=__cosf(th), st=__sinf(th);
    float xtv =  xx*ct + yy*st;
    float ytv = -xx*st + yy*ct;
    float env = __expf(-(xtv*xtv + g*g*ytv*ytv)/(2.f*s*s));
    float phase = 2.f*(float)M_PI*xtv/l + ps;
    s_gr[o][tap] = env*__cosf(phase);
    s_gi[o][tap] = env*__sinf(phase);
  }
  if (t<160){
    int grp = t>>5, e0 = t&31;
    float acc=0.f;
    if (grp==0){
      #pragma unroll
      for(int c=0;c<32;c++) acc += in_w[e0*32+c]*qw[c];
      s_aq[e0]=acc;
    } else if (grp==1){
      #pragma unroll
      for(int c=0;c<32;c++) acc += in_w[(32+e0)*32+c]*kvw[c];
      s_ak[e0]=acc;
    } else if (grp==2){
      #pragma unroll
      for(int c=0;c<32;c++) acc += in_w[(64+e0)*32+c]*kvw[c];
      s_av[e0]=acc;
    } else if (grp==3){
      #pragma unroll
      for(int c=0;c<32;c++) acc += in_w[e0*32+c]*qb[c];
      s_cq[e0]=acc + in_b[e0];
    } else {
      #pragma unroll
      for(int c=0;c<32;c++) acc += in_w[(64+e0)*32+c]*kvb[c];
      s_cv[e0]=acc + in_b[64+e0];
    }
  }
  __syncthreads();

  if (t<25){
    float aR=0.f, aI=0.f;
    #pragma unroll
    for (int o=0;o<NORI;o++){ aR += s_w[o]*s_gr[o][t]; aI += s_w[o]*s_gi[o][t]; }
    c_.kri[t] = make_float2(aR, aI);
  }
  const float rs8 = 0.35355339059327373f; // 1/sqrt(8)
  if (t>=32 && t<36){
    int h = t-32;
    float a=0.f, g2=0.f;
    #pragma unroll
    for (int d=0;d<8;d++){ a += s_aq[h*8+d]*s_ak[h*8+d]; g2 += s_cq[h*8+d]*s_ak[h*8+d]; }
    c_.alpha[h]=a*rs8; c_.gam[h]=g2*rs8;
  }
  if (t>=64 && t<192){   // M_h = ow[:, head slice] @ av_h
    int h=(t-64)>>5, e0=(t-64)&31;
    float acc=0.f;
    #pragma unroll
    for (int d=0;d<8;d++) acc += pows[e0*33 + h*8+d]*s_av[h*8+d];
    s_M[h][e0]=acc;
  }
  if (t>=224){           // b0 = ow@cv + ob
    int e0=t-224; float acc=0.f;
    #pragma unroll
    for (int c=0;c<32;c++) acc += pows[e0*33+c]*s_cv[c];
    s_b0[e0]=acc+ob[e0];
  }
  __syncthreads();

  #pragma unroll
  for (int r=0;r<2;r++){
    int idx = t + (r<<8);
    int h = idx>>7, j = idx&127;
    float acc=0.f;
    #pragma unroll
    for (int e1=0;e1<32;e1++) acc += pm1w[j*33+e1]*s_M[h][e1];
    sm_G[h][j]=acc;
  }
  if (t < 128){           // g0 = m1w@b0 + m1b
    float acc=0.f;
    #pragma unroll
    for (int e1=0;e1<32;e1++) acc += pm1w[t*33+e1]*s_b0[e1];
    sm_g0[t] = acc + m1b[t];
  } else {                // v2 = pw @ m2w
    int j=t-128; float acc=0.f;
    #pragma unroll
    for (int e1=0;e1<32;e1++) acc += s_pw[e1]*pm2w[e1*128+j];
    sm_v2[j]=acc;
  }
  if (t<4){               // p_h = pw . M_h
    float acc=0.f;
    #pragma unroll
    for (int e1=0;e1<32;e1++) acc += s_pw[e1]*s_M[t][e1];
    c_.p[t]=acc;
  }
  if (t==4){              // P0 = pw.(b0+m2b) + pb
    float acc=0.f;
    #pragma unroll
    for (int e1=0;e1<32;e1++) acc += s_pw[e1]*(s_b0[e1]+m2b[e1]);
    c_.P0 = acc + pb[0];
  }
  __syncthreads();

  if (t<64){              // interleave constants per hidden pair jp
    int jp=t;
    float* d = c_.cst + jp*12;
    d[0]=sm_g0[2*jp];   d[1]=sm_g0[2*jp+1];
    #pragma unroll
    for (int h=0;h<4;h++){ d[2+2*h]=sm_G[h][2*jp]; d[3+2*h]=sm_G[h][2*jp+1]; }
    d[10]=sm_v2[2*jp];  d[11]=sm_v2[2*jp+1];
  }
}

// ---------------------------------------------------------------------------
// Kernel 2: fused conv + degree-4 moment-series attention + MLP,
// 4 windows per block, 256 threads, grid 4096, 6 CTAs/SM target (42-reg cap).
// Conv: 128 threads, 2 vertically-adjacent pixels each (6-row load reuse);
// one warp per window -> single full-warp moment reduction.
// ---------------------------------------------------------------------------
__global__ void __launch_bounds__(256,6) fused_kernel(const float* __restrict__ x,
                                                      float* __restrict__ out)
{
  __shared__ float xt[432];                // 12 x 36 halo tile for 4 windows
  __shared__ float ds[256];                // detail per (window k, pixel l)
  __shared__ ull  sCC[4][5];               // packed (CN,CD) per window
  __shared__ __align__(16) float ws4[1024];// float4 w per (k,l)
  __shared__ float ysp[4][256];            // phase-3 partials per window
  __shared__ __align__(16) float cst[768];
  __shared__ ull skri[25];
  __shared__ float sAl[4], sGa[4], sP[4];
  __shared__ float sP0;

  int t = threadIdx.x;
  int lane = t & 31;

  // --- stage constants ---
  if (t<192)       ((float4*)cst)[t] = ((const float4*)c_.cst)[t];
  else if (t<217)  skri[t-192] = ((const ull*)c_.kri)[t-192];
  else if (t<221)  sAl[t-217]=c_.alpha[t-217];
  else if (t<225)  sGa[t-221]=c_.gam[t-221];
  else if (t<229)  sP[t-225]=c_.p[t-225];
  else if (t==229) sP0=c_.P0;

  int wid0 = blockIdx.x<<2;                 // 4 adjacent windows, same row
  int b = wid0>>12, wy=(wid0>>6)&63, wx0=wid0&63;
  int gy0=(wy<<3)-2, gx0=(wx0<<3)-2;
  const float* xb = x + (b<<18);

  // --- halo tile 12x36 ---
  #pragma unroll
  for (int rr=0; rr<2; rr++){
    int idx = t + (rr<<8);
    if (idx < 432){
      int r = idx/36, c = idx-36*r;
      int gy = gy0+r, gx = gx0+c;
      bool ok = ((unsigned)gy<512u) && ((unsigned)gx<512u);
      xt[idx] = ok ? __ldg(xb + gy*512 + gx) : 0.f;
    }
  }
  __syncthreads();

  // --- conv: 128 threads, 2 vertical pixels each; warp k owns window k ---
  if (t < 128){
    int k = t>>5;                    // window (= warp)
    int rp = (lane>>3), cc = lane&7; // row pair 0..3, column 0..7
    int r0 = rp<<1;                  // rows r0, r0+1
    int col0 = (k<<3) + cc;
    ull a0=0ULL, a1=0ULL;
    #pragma unroll
    for (int ii=0; ii<6; ii++){
      float v[5];
      #pragma unroll
      for (int j=0;j<5;j++) v[j] = xt[(r0+ii)*36 + col0 + j];
      if (ii<5){
        #pragma unroll
        for (int j=0;j<5;j++) a0 = fma2(pk(v[j],v[j]), skri[ii*5+j], a0);
      }
      if (ii>=1){
        #pragma unroll
        for (int j=0;j<5;j++) a1 = fma2(pk(v[j],v[j]), skri[(ii-1)*5+j], a1);
      }
    }
    float br0, di0, br1, di1;
    upk(a0, br0, di0); upk(a1, br1, di1);
    int l0 = (rp<<4) + cc;
    ds[(k<<6)+l0]   = di0;
    ds[(k<<6)+l0+8] = di1;
    // moments p=1..5 over both pixels, then full-warp reduce
    float p0a=br0, p1a=br0*br0, p2a=p1a*br0, p3a=p1a*p1a, p4a=p3a*br0;
    float p0b=br1, p1b=br1*br1, p2b=p1b*br1, p3b=p1b*p1b, p4b=p3b*br1;
    float v0=p0a+p0b, v1=p1a+p1b, v2=p2a+p2b, v3=p3a+p3b, v4=p4a+p4b;
    #pragma unroll
    for (int o=16;o>0;o>>=1){
      v0 += __shfl_xor_sync(0xffffffffu, v0, o);
      v1 += __shfl_xor_sync(0xffffffffu, v1, o);
      v2 += __shfl_xor_sync(0xffffffffu, v2, o);
      v3 += __shfl_xor_sync(0xffffffffu, v3, o);
      v4 += __shfl_xor_sync(0xffffffffu, v4, o);
    }
    if (lane==0){
      const float i2=0.5f, i3=1.f/6.f, i4=1.f/24.f;
      sCC[k][0] = pk(v0, 64.f);
      sCC[k][1] = pk(v1, v0);
      sCC[k][2] = pk(v2*i2, v1*i2);
      sCC[k][3] = pk(v3*i3, v2*i3);
      sCC[k][4] = pk(v4*i4, v3*i4);
    }
  }
  __syncthreads();

  { // Horner (degree 4) for all 4 windows: thread = (h=t>>6, l=t&63)
    int h=t>>6, l=t&63;
    float alh=sAl[h], gah=sGa[h];
    #pragma unroll
    for (int k=0;k<4;k++){
      float s = fmaf(alh, ds[(k<<6)+l], gah);
      ull s2 = pk(s,s);
      ull nd = sCC[k][4];
      #pragma unroll
      for (int kk=3;kk>=0;kk--) nd = fma2(nd, s2, sCC[k][kk]);
      float num, den; upk(nd, num, den);
      ws4[(k<<8)+(l<<2)+h] = __fdividef(num, den);
    }
  }
  __syncthreads();

  { // phase 3: thread (q=t>>6, l=t&63); 16 jp x 3 broadcast loads serve 4 windows
    int q=t>>6, l=t&63;
    ull W[4][4];
    #pragma unroll
    for (int k=0;k<4;k++){
      float4 a = ((const float4*)ws4)[(k<<6)+l];
      W[k][0]=pk(a.x,a.x); W[k][1]=pk(a.y,a.y); W[k][2]=pk(a.z,a.z); W[k][3]=pk(a.w,a.w);
    }
    ull acc[4] = {0ULL,0ULL,0ULL,0ULL};
    const float* cp = cst + q*192;
    #pragma unroll
    for (int jp=0;jp<16;jp++){
      ulonglong2 A0 = *(const ulonglong2*)(cp + jp*12);
      ulonglong2 A1 = *(const ulonglong2*)(cp + jp*12 + 4);
      ulonglong2 A2 = *(const ulonglong2*)(cp + jp*12 + 8);
      #pragma unroll
      for (int k=0;k<4;k++){
        ull h2 = fma2(W[k][0], A0.y, A0.x);
        h2 = fma2(W[k][1], A1.x, h2);
        h2 = fma2(W[k][2], A1.y, h2);
        h2 = fma2(W[k][3], A2.x, h2);
        float ha,hb; upk(h2,ha,hb);
        acc[k] = fma2(A2.y, pk(fmaxf(ha,0.f), fmaxf(hb,0.f)), acc[k]);
      }
    }
    #pragma unroll
    for (int k=0;k<4;k++){
      float a0,a1; upk(acc[k],a0,a1);
      ysp[k][t] = a0+a1;
    }
  }
  __syncthreads();

  { // final: thread (k=t>>6, l=t&63): reduce 4 q-partials + tail + store
    int k=t>>6, l=t&63;
    float4 a = ((const float4*)ws4)[(k<<6)+l];
    float y = ysp[k][l] + ysp[k][64+l] + ysp[k][128+l] + ysp[k][192+l]
            + a.x*sP[0] + a.y*sP[1] + a.z*sP[2] + a.w*sP[3]
            + sP0 + ds[(k<<6)+l];
    int r=l>>3, cc=l&7;
    out[(b<<18) + (gy0+2+r)*512 + (gx0+2+(k<<3)+cc)] = y;
  }
}

// ---------------------------------------------------------------------------
extern "C" void kernel_launch(void* const* d_in, const int* in_sizes, int n_in,
                              void* d_out, int out_size)
{
  (void)in_sizes; (void)n_in; (void)out_size;
  const float* x     = (const float*)d_in[0];
  const float* sigma = (const float*)d_in[1];
  const float* lambd = (const float*)d_in[2];
  const float* psi   = (const float*)d_in[3];
  const float* gam   = (const float*)d_in[4];
  const float* theta = (const float*)d_in[5];
  const float* dirw  = (const float*)d_in[6];
  const float* qw    = (const float*)d_in[7];
  const float* qb    = (const float*)d_in[8];
  const float* kvw   = (const float*)d_in[9];
  const float* kvb   = (const float*)d_in[10];
  const float* in_w  = (const float*)d_in[11];
  const float* in_b  = (const float*)d_in[12];
  const float* ow    = (const float*)d_in[13];
  const float* ob    = (const float*)d_in[14];
  const float* m1w   = (const float*)d_in[15];
  const float* m1b   = (const float*)d_in[16];
  const float* m2w   = (const float*)d_in[17];
  const float* m2b   = (const float*)d_in[18];
  const float* pw    = (const float*)d_in[19];
  const float* pb    = (const float*)d_in[20];

  precompute_kernel<<<1,256>>>(sigma,lambd,psi,gam,theta,dirw,qw,qb,kvw,kvb,
                               in_w,in_b,ow,ob,m1w,m1b,m2w,m2b,pw,pb);
  fused_kernel<<<4096,256>>>(x, (float*)d_out);
}

// round 15
// speedup vs baseline: 1.1758x; 1.1758x over previous
#include <cuda_runtime.h>
#include <math.h>

#define NORI 6

typedef unsigned long long ull;

struct __align__(16) Consts {
  float cst[768];        // [jp][12] = {g0 x2, G0 x2, G1 x2, G2 x2, G3 x2, v2 x2}
  float2 kri[25];        // interleaved (kr, ki)
  float alpha[4], gam[4], p[4];
  float P0;
};
__device__ Consts c_;

__device__ __forceinline__ ull pk(float a, float b){ ull r; asm("mov.b64 %0,{%1,%2};":"=l"(r):"f"(a),"f"(b)); return r; }
__device__ __forceinline__ void upk(ull v, float&a, float&b){ asm("mov.b64 {%0,%1},%2;":"=f"(a),"=f"(b):"l"(v)); }
__device__ __forceinline__ ull fma2(ull a, ull b, ull c){ ull d; asm("fma.rn.f32x2 %0,%1,%2,%3;":"=l"(d):"l"(a),"l"(b),"l"(c)); return d; }

__device__ __forceinline__ float softplusf(float x){
  return (x > 20.f) ? x : log1pf(__expf(x));
}

// ---------------------------------------------------------------------------
// Kernel 1: fold all weights into constants (1 block, 512 thr, smem-staged)
// ---------------------------------------------------------------------------
__global__ void __launch_bounds__(512) precompute_kernel(
  const float* __restrict__ sigma, const float* __restrict__ lambd,
  const float* __restrict__ psi,   const float* __restrict__ gamma_,
  const float* __restrict__ theta, const float* __restrict__ dir_w,
  const float* __restrict__ qw,    const float* __restrict__ qb,
  const float* __restrict__ kvw,   const float* __restrict__ kvb,
  const float* __restrict__ in_w,  const float* __restrict__ in_b,
  const float* __restrict__ ow,    const float* __restrict__ ob,
  const float* __restrict__ m1w,   const float* __restrict__ m1b,
  const float* __restrict__ m2w,   const float* __restrict__ m2b,
  const float* __restrict__ pw,    const float* __restrict__ pb)
{
  __shared__ float pm1w[128*33];       // padded rows: [j][33]
  __shared__ float pm2w[4096];         // linear [e1*128+j]
  __shared__ float pows[32*33];        // padded rows: [e0][33]
  __shared__ float s_pw[32];
  __shared__ float s_w[NORI];
  __shared__ float s_gr[NORI][25], s_gi[NORI][25];
  __shared__ float s_aq[32], s_ak[32], s_av[32], s_cq[32], s_cv[32];
  __shared__ float s_M[4][32], s_b0[32];
  __shared__ float sm_G[4][128], sm_g0[128], sm_v2[128];
  int t = threadIdx.x;

  #pragma unroll
  for (int i=0;i<8;i++){
    int idx = t + (i<<9);
    pm1w[(idx>>5)*33 + (idx&31)] = m1w[idx];
  }
  #pragma unroll
  for (int i=0;i<2;i++){
    ((float4*)pm2w)[t + (i<<9)] = ((const float4*)m2w)[t + (i<<9)];
  }
  #pragma unroll
  for (int i=0;i<2;i++){
    int idx = t + (i<<9);
    pows[(idx>>5)*33 + (idx&31)] = ow[idx];
  }
  if (t<32) s_pw[t] = pw[t];

  if (t==0){
    float mx = dir_w[0];
    for (int o=1;o<NORI;o++) mx = fmaxf(mx, dir_w[o]);
    float e[NORI]; float sum=0.f;
    for (int o=0;o<NORI;o++){ e[o]=__expf(dir_w[o]-mx); sum+=e[o]; }
    float inv = 1.f/sum;
    for (int o=0;o<NORI;o++) s_w[o]=e[o]*inv;
  }
  if (t<150){
    int o = t/25, tap = t-25*o;
    int i = tap/5, j = tap-5*i;
    float yy = -1.f + 0.5f*(float)i;
    float xx = -1.f + 0.5f*(float)j;
    float s  = softplusf(sigma[o])+0.1f;
    float l  = softplusf(lambd[o])+0.1f;
    float g  = softplusf(gamma_[o])+0.1f;
    float th = tanhf(theta[o])*(float)M_PI;
    float ps = tanhf(psi[o])*(float)M_PI;
    float ct=__cosf(th), st=__sinf(th);
    float xtv =  xx*ct + yy*st;
    float ytv = -xx*st + yy*ct;
    float env = __expf(-(xtv*xtv + g*g*ytv*ytv)/(2.f*s*s));
    float phase = 2.f*(float)M_PI*xtv/l + ps;
    s_gr[o][tap] = env*__cosf(phase);
    s_gi[o][tap] = env*__sinf(phase);
  }
  if (t>=256 && t<416){
    int grp = (t-256)>>5, e0 = t&31;
    float acc=0.f;
    if (grp==0){
      #pragma unroll
      for(int c=0;c<32;c++) acc += in_w[e0*32+c]*qw[c];
      s_aq[e0]=acc;
    } else if (grp==1){
      #pragma unroll
      for(int c=0;c<32;c++) acc += in_w[(32+e0)*32+c]*kvw[c];
      s_ak[e0]=acc;
    } else if (grp==2){
      #pragma unroll
      for(int c=0;c<32;c++) acc += in_w[(64+e0)*32+c]*kvw[c];
      s_av[e0]=acc;
    } else if (grp==3){
      #pragma unroll
      for(int c=0;c<32;c++) acc += in_w[e0*32+c]*qb[c];
      s_cq[e0]=acc + in_b[e0];
    } else {
      #pragma unroll
      for(int c=0;c<32;c++) acc += in_w[(64+e0)*32+c]*kvb[c];
      s_cv[e0]=acc + in_b[64+e0];
    }
  }
  __syncthreads();

  if (t<25){
    float aR=0.f, aI=0.f;
    #pragma unroll
    for (int o=0;o<NORI;o++){ aR += s_w[o]*s_gr[o][t]; aI += s_w[o]*s_gi[o][t]; }
    c_.kri[t] = make_float2(aR, aI);
  }
  const float rs8 = 0.35355339059327373f; // 1/sqrt(8)
  if (t>=32 && t<36){
    int h = t-32;
    float a=0.f, g2=0.f;
    #pragma unroll
    for (int d=0;d<8;d++){ a += s_aq[h*8+d]*s_ak[h*8+d]; g2 += s_cq[h*8+d]*s_ak[h*8+d]; }
    c_.alpha[h]=a*rs8; c_.gam[h]=g2*rs8;
  }
  if (t>=64 && t<192){   // M_h = ow[:, head slice] @ av_h
    int h=(t-64)>>5, e0=(t-64)&31;
    float acc=0.f;
    #pragma unroll
    for (int d=0;d<8;d++) acc += pows[e0*33 + h*8+d]*s_av[h*8+d];
    s_M[h][e0]=acc;
  }
  if (t>=224 && t<256){  // b0 = ow@cv + ob
    int e0=t-224; float acc=0.f;
    #pragma unroll
    for (int c=0;c<32;c++) acc += pows[e0*33+c]*s_cv[c];
    s_b0[e0]=acc+ob[e0];
  }
  __syncthreads();

  {                      // G_h = m1w @ M_h (512 values, one pass)
    int h = t>>7, j = t&127;
    float acc=0.f;
    #pragma unroll
    for (int e1=0;e1<32;e1++) acc += pm1w[j*33+e1]*s_M[h][e1];
    sm_G[h][j]=acc;
  }
  if (t < 128){           // g0 = m1w@b0 + m1b
    float acc=0.f;
    #pragma unroll
    for (int e1=0;e1<32;e1++) acc += pm1w[t*33+e1]*s_b0[e1];
    sm_g0[t] = acc + m1b[t];
  } else if (t < 256){    // v2 = pw @ m2w
    int j=t-128; float acc=0.f;
    #pragma unroll
    for (int e1=0;e1<32;e1++) acc += s_pw[e1]*pm2w[e1*128+j];
    sm_v2[j]=acc;
  }
  if (t>=256 && t<260){   // p_h = pw . M_h
    int h=t-256; float acc=0.f;
    #pragma unroll
    for (int e1=0;e1<32;e1++) acc += s_pw[e1]*s_M[h][e1];
    c_.p[h]=acc;
  }
  if (t==260){            // P0 = pw.(b0+m2b) + pb
    float acc=0.f;
    #pragma unroll
    for (int e1=0;e1<32;e1++) acc += s_pw[e1]*(s_b0[e1]+m2b[e1]);
    c_.P0 = acc + pb[0];
  }
  __syncthreads();

  if (t<64){              // interleave constants per hidden pair jp
    int jp=t;
    float* d = c_.cst + jp*12;
    d[0]=sm_g0[2*jp];   d[1]=sm_g0[2*jp+1];
    #pragma unroll
    for (int h=0;h<4;h++){ d[2+2*h]=sm_G[h][2*jp]; d[3+2*h]=sm_G[h][2*jp+1]; }
    d[10]=sm_v2[2*jp];  d[11]=sm_v2[2*jp+1];
  }
}

// ---------------------------------------------------------------------------
// Kernel 2: fused conv + degree-4 moment-series attention + MLP,
// 4 windows per block, 256 threads, grid 4096, 5 CTAs/SM (R12 config, no spill)
// ---------------------------------------------------------------------------
__global__ void __launch_bounds__(256,5) fused_kernel(const float* __restrict__ x,
                                                      float* __restrict__ out)
{
  __shared__ float xt[432];                // 12 x 36 halo tile for 4 windows
  __shared__ float ds[256];                // detail per (window k, pixel l)
  __shared__ ull  sCC[4][5];               // packed (CN,CD) per window
  __shared__ __align__(16) float ws4[1024];// float4 w per (k,l)
  __shared__ float ysp[4][256];            // phase-3 partials per window
  __shared__ __align__(16) float cst[768];
  __shared__ ull skri[25];
  __shared__ float sAl[4], sGa[4], sP[4];
  __shared__ float sP0;

  int t = threadIdx.x;
  int lane = t & 31;

  // --- stage constants ---
  if (t<192)       ((float4*)cst)[t] = ((const float4*)c_.cst)[t];
  else if (t<217)  skri[t-192] = ((const ull*)c_.kri)[t-192];
  else if (t<221)  sAl[t-217]=c_.alpha[t-217];
  else if (t<225)  sGa[t-221]=c_.gam[t-221];
  else if (t<229)  sP[t-225]=c_.p[t-225];
  else if (t==229) sP0=c_.P0;

  int wid0 = blockIdx.x<<2;                 // 4 adjacent windows, same row
  int b = wid0>>12, wy=(wid0>>6)&63, wx0=wid0&63;
  int gy0=(wy<<3)-2, gx0=(wx0<<3)-2;
  const float* xb = x + (b<<18);

  // --- halo tile 12x36 ---
  #pragma unroll
  for (int rr=0; rr<2; rr++){
    int idx = t + (rr<<8);
    if (idx < 432){
      int r = idx/36, c = idx-36*r;
      int gy = gy0+r, gx = gx0+c;
      bool ok = ((unsigned)gy<512u) && ((unsigned)gx<512u);
      xt[idx] = ok ? __ldg(xb + gy*512 + gx) : 0.f;
    }
  }
  __syncthreads();

  // --- conv: 128 threads, 2 vertical pixels each; warp k owns window k ---
  if (t < 128){
    int k = t>>5;                    // window (= warp)
    int rp = (lane>>3), cc = lane&7; // row pair 0..3, column 0..7
    int r0 = rp<<1;                  // rows r0, r0+1
    int col0 = (k<<3) + cc;
    ull a0=0ULL, a1=0ULL;
    #pragma unroll
    for (int ii=0; ii<6; ii++){
      float v[5];
      #pragma unroll
      for (int j=0;j<5;j++) v[j] = xt[(r0+ii)*36 + col0 + j];
      if (ii<5){
        #pragma unroll
        for (int j=0;j<5;j++) a0 = fma2(pk(v[j],v[j]), skri[ii*5+j], a0);
      }
      if (ii>=1){
        #pragma unroll
        for (int j=0;j<5;j++) a1 = fma2(pk(v[j],v[j]), skri[(ii-1)*5+j], a1);
      }
    }
    float br0, di0, br1, di1;
    upk(a0, br0, di0); upk(a1, br1, di1);
    int l0 = (rp<<4) + cc;
    ds[(k<<6)+l0]   = di0;
    ds[(k<<6)+l0+8] = di1;
    // moments p=1..5 over both pixels, then full-warp reduce
    float p0a=br0, p1a=br0*br0, p2a=p1a*br0, p3a=p1a*p1a, p4a=p3a*br0;
    float p0b=br1, p1b=br1*br1, p2b=p1b*br1, p3b=p1b*p1b, p4b=p3b*br1;
    float v0=p0a+p0b, v1=p1a+p1b, v2=p2a+p2b, v3=p3a+p3b, v4=p4a+p4b;
    #pragma unroll
    for (int o=16;o>0;o>>=1){
      v0 += __shfl_xor_sync(0xffffffffu, v0, o);
      v1 += __shfl_xor_sync(0xffffffffu, v1, o);
      v2 += __shfl_xor_sync(0xffffffffu, v2, o);
      v3 += __shfl_xor_sync(0xffffffffu, v3, o);
      v4 += __shfl_xor_sync(0xffffffffu, v4, o);
    }
    if (lane==0){
      const float i2=0.5f, i3=1.f/6.f, i4=1.f/24.f;
      sCC[k][0] = pk(v0, 64.f);
      sCC[k][1] = pk(v1, v0);
      sCC[k][2] = pk(v2*i2, v1*i2);
      sCC[k][3] = pk(v3*i3, v2*i3);
      sCC[k][4] = pk(v4*i4, v3*i4);
    }
  }
  __syncthreads();

  { // Horner (degree 4) for all 4 windows: thread = (h=t>>6, l=t&63)
    int h=t>>6, l=t&63;
    float alh=sAl[h], gah=sGa[h];
    #pragma unroll
    for (int k=0;k<4;k++){
      float s = fmaf(alh, ds[(k<<6)+l], gah);
      ull s2 = pk(s,s);
      ull nd = sCC[k][4];
      #pragma unroll
      for (int kk=3;kk>=0;kk--) nd = fma2(nd, s2, sCC[k][kk]);
      float num, den; upk(nd, num, den);
      ws4[(k<<8)+(l<<2)+h] = __fdividef(num, den);
    }
  }
  __syncthreads();

  { // phase 3: thread (q=t>>6, l=t&63); 16 jp x 3 broadcast loads serve 4 windows
    int q=t>>6, l=t&63;
    ull W[4][4];
    #pragma unroll
    for (int k=0;k<4;k++){
      float4 a = ((const float4*)ws4)[(k<<6)+l];
      W[k][0]=pk(a.x,a.x); W[k][1]=pk(a.y,a.y); W[k][2]=pk(a.z,a.z); W[k][3]=pk(a.w,a.w);
    }
    ull acc[4] = {0ULL,0ULL,0ULL,0ULL};
    const float* cp = cst + q*192;
    #pragma unroll
    for (int jp=0;jp<16;jp++){
      ulonglong2 A0 = *(const ulonglong2*)(cp + jp*12);
      ulonglong2 A1 = *(const ulonglong2*)(cp + jp*12 + 4);
      ulonglong2 A2 = *(const ulonglong2*)(cp + jp*12 + 8);
      #pragma unroll
      for (int k=0;k<4;k++){
        ull h2 = fma2(W[k][0], A0.y, A0.x);
        h2 = fma2(W[k][1], A1.x, h2);
        h2 = fma2(W[k][2], A1.y, h2);
        h2 = fma2(W[k][3], A2.x, h2);
        float ha,hb; upk(h2,ha,hb);
        acc[k] = fma2(A2.y, pk(fmaxf(ha,0.f), fmaxf(hb,0.f)), acc[k]);
      }
    }
    #pragma unroll
    for (int k=0;k<4;k++){
      float a0,a1; upk(acc[k],a0,a1);
      ysp[k][t] = a0+a1;
    }
  }
  __syncthreads();

  { // final: thread (k=t>>6, l=t&63): reduce 4 q-partials + tail + store
    int k=t>>6, l=t&63;
    float4 a = ((const float4*)ws4)[(k<<6)+l];
    float y = ysp[k][l] + ysp[k][64+l] + ysp[k][128+l] + ysp[k][192+l]
            + a.x*sP[0] + a.y*sP[1] + a.z*sP[2] + a.w*sP[3]
            + sP0 + ds[(k<<6)+l];
    int r=l>>3, cc=l&7;
    out[(b<<18) + (gy0+2+r)*512 + (gx0+2+(k<<3)+cc)] = y;
  }
}

// ---------------------------------------------------------------------------
extern "C" void kernel_launch(void* const* d_in, const int* in_sizes, int n_in,
                              void* d_out, int out_size)
{
  (void)in_sizes; (void)n_in; (void)out_size;
  const float* x     = (const float*)d_in[0];
  const float* sigma = (const float*)d_in[1];
  const float* lambd = (const float*)d_in[2];
  const float* psi   = (const float*)d_in[3];
  const float* gam   = (const float*)d_in[4];
  const float* theta = (const float*)d_in[5];
  const float* dirw  = (const float*)d_in[6];
  const float* qw    = (const float*)d_in[7];
  const float* qb    = (const float*)d_in[8];
  const float* kvw   = (const float*)d_in[9];
  const float* kvb   = (const float*)d_in[10];
  const float* in_w  = (const float*)d_in[11];
  const float* in_b  = (const float*)d_in[12];
  const float* ow    = (const float*)d_in[13];
  const float* ob    = (const float*)d_in[14];
  const float* m1w   = (const float*)d_in[15];
  const float* m1b   = (const float*)d_in[16];
  const float* m2w   = (const float*)d_in[17];
  const float* m2b   = (const float*)d_in[18];
  const float* pw    = (const float*)d_in[19];
  const float* pb    = (const float*)d_in[20];

  precompute_kernel<<<1,512>>>(sigma,lambd,psi,gam,theta,dirw,qw,qb,kvw,kvb,
                               in_w,in_b,ow,ob,m1w,m1b,m2w,m2b,pw,pb);
  fused_kernel<<<4096,256>>>(x, (float*)d_out);
}